// round 1
// baseline (speedup 1.0000x reference)
#include <cuda_runtime.h>
#include <cstdint>

#define NX 100000
#define NC 50000
#define NR 1000
#define HID 64

// Scratch (allocation-free rule: __device__ globals)
__device__ __align__(16) float g_h_xx[NX * HID];
__device__ __align__(16) float g_h_cx[NC * HID];
__device__ __align__(16) float g_h_rx[NR * HID];
__device__ __align__(16) float g_agg[NX * HID];

// ---------------------------------------------------------------------------
// Fused Linear (+optional ReLU): Y[N,64] = act(X[N,K] @ W[64,K]^T + b[64])
// Tile: 256 rows x 64 cols per block, 256 threads.
// Thread: 4 rows x 16 cols (acc[4][16]).  X and W^T staged in smem.
// Xs stride = K+1 (bank-conflict-free row reads), Ws stride = 68 (16B-aligned pad).
// ---------------------------------------------------------------------------
template <bool RELU>
__global__ void linear_kernel(const float* __restrict__ X,
                              const float* __restrict__ W,
                              const float* __restrict__ B,
                              float* __restrict__ Y,
                              int N, int K) {
    extern __shared__ float smem[];
    const int XS_STRIDE = K + 1;
    float* Xs = smem;                       // [256][K+1]
    float* Ws = smem + 256 * XS_STRIDE;     // [K][68]  (Ws[k*68+j] = W[j][k])

    const int tid  = threadIdx.x;
    const int row0 = blockIdx.x * 256;

    // Stage W transposed
    for (int idx = tid; idx < 64 * K; idx += 256) {
        int j = idx / K;
        int k = idx - j * K;
        Ws[k * 68 + j] = W[idx];
    }
    // Stage X rows (zero-pad tail rows)
    for (int idx = tid; idx < 256 * K; idx += 256) {
        int r = idx / K;
        int k = idx - r * K;
        int gr = row0 + r;
        Xs[r * XS_STRIDE + k] = (gr < N) ? X[(size_t)gr * K + k] : 0.0f;
    }
    __syncthreads();

    const int cg = tid & 3;    // col group: cols [cg*16, cg*16+16)
    const int rg = tid >> 2;   // row group: rows [rg*4, rg*4+4)

    float acc[4][16];
#pragma unroll
    for (int i = 0; i < 4; ++i)
#pragma unroll
        for (int j = 0; j < 16; ++j) acc[i][j] = 0.0f;

    const float* wp = Ws + cg * 16;
    const float* xp = Xs + rg * 4 * XS_STRIDE;

#pragma unroll 4
    for (int k = 0; k < K; ++k) {
        float wv[16];
        *(float4*)(wv)      = *(const float4*)(wp + k * 68);
        *(float4*)(wv + 4)  = *(const float4*)(wp + k * 68 + 4);
        *(float4*)(wv + 8)  = *(const float4*)(wp + k * 68 + 8);
        *(float4*)(wv + 12) = *(const float4*)(wp + k * 68 + 12);
#pragma unroll
        for (int i = 0; i < 4; ++i) {
            float xv = xp[i * XS_STRIDE + k];
#pragma unroll
            for (int j = 0; j < 16; ++j) acc[i][j] += xv * wv[j];
        }
    }

    // Epilogue: bias (+ReLU), vectorized store
    float bb[16];
    *(float4*)(bb)      = *(const float4*)(B + cg * 16);
    *(float4*)(bb + 4)  = *(const float4*)(B + cg * 16 + 4);
    *(float4*)(bb + 8)  = *(const float4*)(B + cg * 16 + 8);
    *(float4*)(bb + 12) = *(const float4*)(B + cg * 16 + 12);

#pragma unroll
    for (int i = 0; i < 4; ++i) {
        int gr = row0 + rg * 4 + i;
        if (gr >= N) continue;
        float o[16];
#pragma unroll
        for (int j = 0; j < 16; ++j) {
            float v = acc[i][j] + bb[j];
            o[j] = RELU ? (v > 0.0f ? v : 0.0f) : v;
        }
        float4* yp = (float4*)(Y + (size_t)gr * 64 + cg * 16);
        yp[0] = *(float4*)(o);
        yp[1] = *(float4*)(o + 4);
        yp[2] = *(float4*)(o + 8);
        yp[3] = *(float4*)(o + 12);
    }
}

// ---------------------------------------------------------------------------
// Scatter-add: agg[dst[e]] += h[src[e]]  (64 floats per edge)
// 16 threads per edge, one float4 each, vector reduction to L2.
// ---------------------------------------------------------------------------
__global__ void scatter_kernel(const float* __restrict__ h,
                               const int* __restrict__ src,
                               const int* __restrict__ dst,
                               int E, float* __restrict__ agg) {
    long long gt = (long long)blockIdx.x * blockDim.x + threadIdx.x;
    int edge = (int)(gt >> 4);
    int lane = (int)(gt & 15);
    if (edge >= E) return;
    int s = src[edge];
    int d = dst[edge];
    float4 v = ((const float4*)h)[(size_t)s * 16 + lane];
    float4* p = ((float4*)agg) + (size_t)d * 16 + lane;
    asm volatile("red.global.add.v4.f32 [%0], {%1, %2, %3, %4};"
                 :: "l"(p), "f"(v.x), "f"(v.y), "f"(v.z), "f"(v.w)
                 : "memory");
}

extern "C" void kernel_launch(void* const* d_in, const int* in_sizes, int n_in,
                              void* d_out, int out_size) {
    const float* x      = (const float*)d_in[0];
    const float* c      = (const float*)d_in[1];
    const float* r      = (const float*)d_in[2];
    const int* e_xx_s   = (const int*)d_in[3];
    const int* e_xx_d   = (const int*)d_in[4];
    const int* e_cx_s   = (const int*)d_in[5];
    const int* e_cx_d   = (const int*)d_in[6];
    const int* e_rx_s   = (const int*)d_in[7];
    const int* e_rx_d   = (const int*)d_in[8];
    const float* W_x    = (const float*)d_in[9];
    const float* b_x    = (const float*)d_in[10];
    const float* W_c    = (const float*)d_in[11];
    const float* b_c    = (const float*)d_in[12];
    const float* W_r    = (const float*)d_in[13];
    const float* b_r    = (const float*)d_in[14];
    const float* W_xx   = (const float*)d_in[15];
    const float* b_xx   = (const float*)d_in[16];
    const float* W_cx   = (const float*)d_in[17];
    const float* b_cx   = (const float*)d_in[18];
    const float* W_rx   = (const float*)d_in[19];
    const float* b_rx   = (const float*)d_in[20];
    const float* W_pool = (const float*)d_in[21];
    const float* b_pool = (const float*)d_in[22];
    float* out = (float*)d_out;

    const int E_xx = in_sizes[3];
    const int E_cx = in_sizes[5];
    const int E_rx = in_sizes[7];

    void* p;
    cudaGetSymbolAddress(&p, g_h_xx); float* h_xx = (float*)p;
    cudaGetSymbolAddress(&p, g_h_cx); float* h_cx = (float*)p;
    cudaGetSymbolAddress(&p, g_h_rx); float* h_rx = (float*)p;
    cudaGetSymbolAddress(&p, g_agg);  float* agg  = (float*)p;

    const int shb64 = (256 * 65 + 64 * 68) * 4;   // 83,968 B
    const int shb32 = (256 * 33 + 32 * 68) * 4;
    const int shb48 = (256 * 49 + 48 * 68) * 4;
    cudaFuncSetAttribute((const void*)linear_kernel<true>,
                         cudaFuncAttributeMaxDynamicSharedMemorySize, shb64);
    cudaFuncSetAttribute((const void*)linear_kernel<false>,
                         cudaFuncAttributeMaxDynamicSharedMemorySize, shb64);

    const int OFF_C = NX * 64;
    const int OFF_R = NX * 64 + NC * 64;

    dim3 blk(256);
    int gx = (NX + 255) / 256;
    int gc = (NC + 255) / 256;
    int gr = (NR + 255) / 256;

    // Node-level fused Linear+ReLU (per-node messages, computed once)
    linear_kernel<true><<<gx, blk, shb64>>>(x, W_x,  b_x,  agg,         NX, 64); // self -> agg
    linear_kernel<true><<<gx, blk, shb64>>>(x, W_xx, b_xx, h_xx,        NX, 64);
    linear_kernel<true><<<gc, blk, shb32>>>(c, W_cx, b_cx, h_cx,        NC, 32);
    linear_kernel<true><<<gr, blk, shb48>>>(r, W_rx, b_rx, h_rx,        NR, 48);
    linear_kernel<true><<<gc, blk, shb32>>>(c, W_c,  b_c,  out + OFF_C, NC, 32); // c_out
    linear_kernel<true><<<gr, blk, shb48>>>(r, W_r,  b_r,  out + OFF_R, NR, 48); // r_out

    // Edge scatter-add (L2-resident gather + vector atomics)
    {
        long long t;
        t = (long long)E_xx * 16;
        scatter_kernel<<<(unsigned)((t + 255) / 256), blk>>>(h_xx, e_xx_s, e_xx_d, E_xx, agg);
        t = (long long)E_cx * 16;
        scatter_kernel<<<(unsigned)((t + 255) / 256), blk>>>(h_cx, e_cx_s, e_cx_d, E_cx, agg);
        t = (long long)E_rx * 16;
        scatter_kernel<<<(unsigned)((t + 255) / 256), blk>>>(h_rx, e_rx_s, e_rx_d, E_rx, agg);
    }

    // Pool: x_out = agg @ W_pool^T + b_pool (no ReLU)
    linear_kernel<false><<<gx, blk, shb64>>>(agg, W_pool, b_pool, out, NX, 64);
}